// round 16
// baseline (speedup 1.0000x reference)
#include <cuda_runtime.h>
#include <cuda_fp16.h>
#include <cstdint>
#include <math.h>

#define HH 128
#define WW 128
#define HWP 16384
#define BATCH 4
#define KIDS 20

// ---------------- scratch (device globals; no allocation) ----------------
__device__ __half g_x16[BATCH * 512 * HWP];    // 67 MB fp16 input copy
__device__ __half g_buf1[BATCH * 256 * HWP];   // 33.5 MB
__device__ __half g_buf2[BATCH * 128 * HWP];   // 16.8 MB
__device__ __half g_buf3[BATCH * 64 * HWP];    // 8.4 MB
__device__ float g_mr[64];                     // mean/rstd pairs
__device__ float g_gnpart[4096];               // GN partial sums
__device__ float g_partial[BATCH * 32 * KIDS * 64];
__device__ float g_pcnt[BATCH * 32 * KIDS];

// ---------------- fp16 helpers ----------------
__device__ __forceinline__ uint32_t pack_f16(float lo, float hi) {
    uint32_t r;
    asm("cvt.rn.f16x2.f32 %0, %1, %2;" : "=r"(r) : "f"(hi), "f"(lo));
    return r;
}
__device__ __forceinline__ void mma_f16(float* c, uint32_t a0, uint32_t a1,
                                        uint32_t a2, uint32_t a3,
                                        uint32_t b0, uint32_t b1) {
    asm volatile("mma.sync.aligned.m16n8k16.row.col.f32.f16.f16.f32 "
                 "{%0,%1,%2,%3}, {%4,%5,%6,%7}, {%8,%9}, {%0,%1,%2,%3};"
                 : "+f"(c[0]), "+f"(c[1]), "+f"(c[2]), "+f"(c[3])
                 : "r"(a0), "r"(a1), "r"(a2), "r"(a3), "r"(b0), "r"(b1));
}

// ---------------- fp32 -> fp16 conversion (input pre-pass) ----------------
__global__ void f2h_kernel(const float* __restrict__ src, __half* __restrict__ dst, int n4)
{
    int i = blockIdx.x * 256 + threadIdx.x;
    if (i < n4) {
        float4 v = reinterpret_cast<const float4*>(src)[i];
        uint2 o;
        o.x = pack_f16(v.x, v.y);
        o.y = pack_f16(v.z, v.w);
        reinterpret_cast<uint2*>(dst)[i] = o;
    }
}

// ---------------- conv as fp16 mma.sync implicit GEMM ----------------
// Round-15: identical GEMM machinery to round 14 (passing). Changes:
//  - B input read from fp16 buffers (LDG.16, half staging bytes)
//  - conv output stored fp16 (half epilogue + downstream bytes)
// GN+ReLU fused into B staging in fp32 math (cvt f16->f32, fma, max, pack),
// applied ONLY in-bounds. smem packed k2-major, conflict-free (mod-32 == 8).
template<int CI, int CO, bool GN>
__global__ __launch_bounds__(256, 2)
void conv_mma_kernel(const __half* __restrict__ in, const float* __restrict__ wgt,
                     const float* __restrict__ bias, __half* __restrict__ out,
                     const float* __restrict__ mr, const float* __restrict__ gw,
                     const float* __restrict__ gb, int Gin)
{
    constexpr int K = CI * 9;
    constexpr int NCHUNK = CI / 16;           // 144 k per chunk
    constexpr int M = (CO < 128) ? CO : 128;
    constexpr int MFRAG = M / 32;
    constexpr int LOG2M = (M == 128) ? 7 : 6;
    constexpr int APAD2 = M + 8;              // k2-major row stride (mod 32 == 8)
    constexpr int BPAD2 = 136;                // k2-major px stride (mod 32 == 8)
    constexpr int A4 = M * 36;                // float4s of A per chunk (144 k)

    extern __shared__ char smem[];
    uint32_t* As2 = reinterpret_cast<uint32_t*>(smem);    // [72][APAD2]
    uint32_t* Bs2 = As2 + 72 * APAD2;                     // [72][BPAD2]
    float* scp = reinterpret_cast<float*>(Bs2 + 72 * BPAD2);   // GN scale [CI]
    float* shp = scp + (GN ? CI : 0);

    const int tile = blockIdx.x;
    const int b = tile >> 7;
    const int y = tile & 127;
    const int m0 = blockIdx.y * M;
    const int tid = threadIdx.x;
    const int lane = tid & 31;
    const int g = lane >> 2;
    const int q = lane & 3;
    const int w = tid >> 5;
    const int warpM = w >> 2;
    const int warpN = w & 3;
    const int m0w = warpM * (M / 2);
    const int n0w = warpN * 32;

    if (GN) {
        const int CPG = CI / Gin;
        for (int c = tid; c < CI; c += 256) {
            int gi = c / CPG;
            float mean = mr[(b * Gin + gi) * 2 + 0];
            float rstd = mr[(b * Gin + gi) * 2 + 1];
            float s = rstd * gw[c];
            scp[c] = s;
            shp[c] = gb[c] - mean * s;
        }
    }

    const __half* inB = in + (size_t)b * CI * HWP;
    const int px = tid & 127;
    const int khalf = tid >> 7;        // 0/1 -> channels 0..7 / 8..15 of chunk

    // hoisted im2col geometry
    const int py[3]  = { (y - 1) * WW, y * WW, (y + 1) * WW };
    const int pxx[3] = { px - 1, px, px + 1 };
    const bool vy[3] = { y > 0, true, y < 127 };
    const bool vx[3] = { px > 0, true, px < 127 };

    // A staging mapping: lane -> row-major
    const int arow = tid & (M - 1);
    const int ak4base = tid >> LOG2M;
    constexpr int ASTRIDE = 256 >> LOG2M;

    float acc[MFRAG][4][4];
#pragma unroll
    for (int mi = 0; mi < MFRAG; mi++)
#pragma unroll
        for (int ni = 0; ni < 4; ni++)
#pragma unroll
            for (int j = 0; j < 4; j++) acc[mi][ni][j] = 0.f;

    for (int chunk = 0; chunk < NCHUNK; chunk++) {
        const int kbase = chunk * 144;
        __syncthreads();   // previous compute done before overwrite

        // ---- stage A (weights fp32 gmem): float4 -> 2 packed f16x2
#pragma unroll
        for (int it = 0; it < (A4 + 255) / 256; it++) {
            int k4 = ak4base + it * ASTRIDE;
            if ((A4 % 256 == 0) || k4 < 36) {
                float4 v = *reinterpret_cast<const float4*>(
                    wgt + (size_t)(m0 + arow) * K + kbase + k4 * 4);
                As2[(2 * k4 + 0) * APAD2 + arow] = pack_f16(v.x, v.y);
                As2[(2 * k4 + 1) * APAD2 + arow] = pack_f16(v.z, v.w);
            }
        }
        // ---- stage B (fp16 gmem, materialized im2col pairs, GN in-bounds)
        {
            const int cib = chunk * 16 + khalf * 8;
            const int k2base = khalf * 36;
            float prev = 0.f;
#pragma unroll
            for (int cloc = 0; cloc < 8; cloc++) {
                const __half* pc = inB + (size_t)(cib + cloc) * HWP;
                float s = 0.f, h = 0.f;
                if (GN) { s = scp[cib + cloc]; h = shp[cib + cloc]; }
#pragma unroll
                for (int t = 0; t < 9; t++) {
                    const int dy = t / 3;          // compile-time
                    const int dx = t - dy * 3;     // compile-time
                    float v = 0.f;
                    if (vy[dy] && vx[dx]) {
                        v = __half2float(pc[py[dy] + pxx[dx]]);
                        if (GN) v = fmaxf(fmaf(v, s, h), 0.f);
                    }
                    const int kkl = cloc * 9 + t;  // compile-time 0..71
                    if ((kkl & 1) == 0) {
                        prev = v;
                    } else {
                        Bs2[(k2base + (kkl >> 1)) * BPAD2 + px] = pack_f16(prev, v);
                    }
                }
            }
        }
        __syncthreads();

        // ---- compute: 9 k16-steps of m16n8k16
#pragma unroll
        for (int ks = 0; ks < 9; ks++) {
            const int k20 = 8 * ks + q;
            uint32_t af[MFRAG][4];
#pragma unroll
            for (int mi = 0; mi < MFRAG; mi++) {
                int row = m0w + mi * 16 + g;
                af[mi][0] = As2[k20 * APAD2 + row];
                af[mi][1] = As2[k20 * APAD2 + row + 8];
                af[mi][2] = As2[(k20 + 4) * APAD2 + row];
                af[mi][3] = As2[(k20 + 4) * APAD2 + row + 8];
            }
#pragma unroll
            for (int ni = 0; ni < 4; ni++) {
                int pxn = n0w + ni * 8 + g;
                uint32_t b0 = Bs2[k20 * BPAD2 + pxn];
                uint32_t b1 = Bs2[(k20 + 4) * BPAD2 + pxn];
#pragma unroll
                for (int mi = 0; mi < MFRAG; mi++)
                    mma_f16(acc[mi][ni], af[mi][0], af[mi][1], af[mi][2], af[mi][3], b0, b1);
            }
        }
    }

    // ---- epilogue: +bias, pack and store NCHW fp16 pairs (4B stores)
#pragma unroll
    for (int mi = 0; mi < MFRAG; mi++) {
        int colo = m0 + m0w + mi * 16 + g;
        int cohi = colo + 8;
        float blo = bias[colo];
        float bhi = bias[cohi];
        __half* dlo = out + (((size_t)(b * CO + colo)) * HH + y) * WW;
        __half* dhi = out + (((size_t)(b * CO + cohi)) * HH + y) * WW;
#pragma unroll
        for (int ni = 0; ni < 4; ni++) {
            int x0 = n0w + ni * 8 + 2 * q;
            *reinterpret_cast<uint32_t*>(dlo + x0) =
                pack_f16(acc[mi][ni][0] + blo, acc[mi][ni][1] + blo);
            *reinterpret_cast<uint32_t*>(dhi + x0) =
                pack_f16(acc[mi][ni][2] + bhi, acc[mi][ni][3] + bhi);
        }
    }
}

// ---------------- GroupNorm statistics: partial pass (fp16 input) ----------------
__global__ void gn_part_kernel(const __half* __restrict__ x, float* __restrict__ part,
                               int Cg, int SL)
{
    const int bg = blockIdx.x / SL;
    const int sl = blockIdx.x % SL;
    const size_t n = (size_t)Cg * HWP;
    const size_t cn = n / SL;
    const uint2* p = reinterpret_cast<const uint2*>(x + (size_t)bg * n + (size_t)sl * cn);
    const int n4 = (int)(cn >> 2);

    float s = 0.f, ss = 0.f;
    for (int i = threadIdx.x; i < n4; i += 256) {
        uint2 u = p[i];
        float2 f0 = __half22float2(*reinterpret_cast<__half2*>(&u.x));
        float2 f1 = __half22float2(*reinterpret_cast<__half2*>(&u.y));
        s  += f0.x + f0.y + f1.x + f1.y;
        ss += f0.x * f0.x + f0.y * f0.y + f1.x * f1.x + f1.y * f1.y;
    }
    __shared__ float sh_s[256], sh_ss[256];
    sh_s[threadIdx.x] = s;
    sh_ss[threadIdx.x] = ss;
    __syncthreads();
    for (int st = 128; st > 0; st >>= 1) {
        if ((int)threadIdx.x < st) {
            sh_s[threadIdx.x]  += sh_s[threadIdx.x + st];
            sh_ss[threadIdx.x] += sh_ss[threadIdx.x + st];
        }
        __syncthreads();
    }
    if (threadIdx.x == 0) {
        part[blockIdx.x * 2 + 0] = sh_s[0];
        part[blockIdx.x * 2 + 1] = sh_ss[0];
    }
}

// ---------------- GroupNorm statistics: final reduce ----------------
__global__ void gn_final_kernel(const float* __restrict__ part, float* __restrict__ mr,
                                int SL, float inv_n)
{
    const int bg = threadIdx.x;
    float s = 0.f, ss = 0.f;
    for (int i = 0; i < SL; i++) {
        s  += part[(bg * SL + i) * 2 + 0];
        ss += part[(bg * SL + i) * 2 + 1];
    }
    float mean = s * inv_n;
    float var = ss * inv_n - mean * mean;
    mr[bg * 2 + 0] = mean;
    mr[bg * 2 + 1] = rsqrtf(var + 1e-5f);
}

// ---------------- masked segment pooling (fp16 input, GN3+ReLU fused) ----------------
__global__ void pool_acc_kernel(const __half* __restrict__ h, const int* __restrict__ masks,
                                const float* __restrict__ mr, const float* __restrict__ gw,
                                const float* __restrict__ gb,
                                float* __restrict__ partial, float* __restrict__ pcnt)
{
    const int b = blockIdx.y;
    const int chunk = blockIdx.x;
    const int tid = threadIdx.x;

    __shared__ float s_sums[KIDS * 65];
    __shared__ float s_cnt[KIDS];
    __shared__ float sc[64], sh[64];
    for (int i = tid; i < KIDS * 65; i += 256) s_sums[i] = 0.f;
    if (tid < KIDS) s_cnt[tid] = 0.f;
    if (tid < 64) {
        int g = tid >> 4;
        float mean = mr[(b * 4 + g) * 2 + 0];
        float rstd = mr[(b * 4 + g) * 2 + 1];
        float s = rstd * gw[tid];
        sc[tid] = s;
        sh[tid] = gb[tid] - mean * s;
    }
    __syncthreads();

    const __half* hb = h + (size_t)b * 64 * HWP;
    const int* mb = masks + b * HWP;

    const int p0 = chunk * 512;
    for (int p = p0 + tid; p < p0 + 512; p += 256) {
        int k = mb[p] - 1;
        if (k >= 0) {
            atomicAdd(&s_cnt[k], 1.f);
#pragma unroll
            for (int c = 0; c < 64; c++) {
                float v = fmaxf(fmaf(__half2float(hb[c * HWP + p]), sc[c], sh[c]), 0.f);
                atomicAdd(&s_sums[k * 65 + c], v);
            }
        }
    }
    __syncthreads();

    float* pb = partial + (size_t)(b * 32 + chunk) * (KIDS * 64);
    for (int i = tid; i < KIDS * 64; i += 256) {
        int k = i >> 6, c = i & 63;
        pb[i] = s_sums[k * 65 + c];
    }
    if (tid < KIDS) pcnt[(b * 32 + chunk) * KIDS + tid] = s_cnt[tid];
}

// ---------------- reduce partials + dense heads ----------------
__global__ void heads_kernel(const float* __restrict__ partial, const float* __restrict__ pcnt,
                             const float* __restrict__ wb, const float* __restrict__ bb,
                             const float* __restrict__ wc, const float* __restrict__ bc,
                             float* __restrict__ out)
{
    const int b = blockIdx.x;
    const int k = blockIdx.y;
    const int c = threadIdx.x;

    float s = 0.f;
    for (int ch = 0; ch < 32; ch++)
        s += partial[(size_t)(b * 32 + ch) * (KIDS * 64) + k * 64 + c];
    float cnt = 0.f;
    for (int ch = 0; ch < 32; ch++)
        cnt += pcnt[(b * 32 + ch) * KIDS + k];
    float pooled = s / (cnt + 1e-6f);

    __shared__ float red[64];
#pragma unroll
    for (int o = 0; o < 7; o++) {
        red[c] = pooled * wb[o * 64 + c];
        __syncthreads();
        for (int st = 32; st > 0; st >>= 1) {
            if (c < st) red[c] += red[c + st];
            __syncthreads();
        }
        if (c == 0) out[(b * KIDS + k) * 7 + o] = red[0] + bb[o];
        __syncthreads();
    }
    red[c] = pooled * wc[c];
    __syncthreads();
    for (int st = 32; st > 0; st >>= 1) {
        if (c < st) red[c] += red[c + st];
        __syncthreads();
    }
    if (c == 0) {
        float z = red[0] + bc[0];
        out[BATCH * KIDS * 7 + b * KIDS + k] = 1.f / (1.f + expf(-z));
    }
}

// ---------------- launch ----------------
extern "C" void kernel_launch(void* const* d_in, const int* in_sizes, int n_in,
                              void* d_out, int out_size)
{
    const float* x    = (const float*)d_in[0];
    const int*   masks= (const int*)  d_in[1];
    const float* w1   = (const float*)d_in[2];
    const float* b1   = (const float*)d_in[3];
    const float* g1w  = (const float*)d_in[4];
    const float* g1b  = (const float*)d_in[5];
    const float* w2   = (const float*)d_in[6];
    const float* b2   = (const float*)d_in[7];
    const float* g2w  = (const float*)d_in[8];
    const float* g2b  = (const float*)d_in[9];
    const float* w3   = (const float*)d_in[10];
    const float* b3   = (const float*)d_in[11];
    const float* g3w  = (const float*)d_in[12];
    const float* g3b  = (const float*)d_in[13];
    const float* wb   = (const float*)d_in[14];
    const float* bb   = (const float*)d_in[15];
    const float* wc   = (const float*)d_in[16];
    const float* bc   = (const float*)d_in[17];
    float* out = (float*)d_out;

    __half *x16, *buf1, *buf2, *buf3;
    float *mr, *gnpart, *partial, *pcnt;
    cudaGetSymbolAddress((void**)&x16, g_x16);
    cudaGetSymbolAddress((void**)&buf1, g_buf1);
    cudaGetSymbolAddress((void**)&buf2, g_buf2);
    cudaGetSymbolAddress((void**)&buf3, g_buf3);
    cudaGetSymbolAddress((void**)&mr, g_mr);
    cudaGetSymbolAddress((void**)&gnpart, g_gnpart);
    cudaGetSymbolAddress((void**)&partial, g_partial);
    cudaGetSymbolAddress((void**)&pcnt, g_pcnt);

    // dynamic smem: 72*APAD2*4 + 72*136*4 + GN arrays
    const int SM1 = 72 * 136 * 4 + 72 * 136 * 4;                 // 78336
    const int SM2 = 72 * 136 * 4 + 72 * 136 * 4 + 2 * 256 * 4;   // 80384
    const int SM3 = 72 * 72 * 4 + 72 * 136 * 4 + 2 * 128 * 4;    // 60928
    cudaFuncSetAttribute(conv_mma_kernel<512, 256, false>,
                         cudaFuncAttributeMaxDynamicSharedMemorySize, SM1);
    cudaFuncSetAttribute(conv_mma_kernel<256, 128, true>,
                         cudaFuncAttributeMaxDynamicSharedMemorySize, SM2);
    cudaFuncSetAttribute(conv_mma_kernel<128, 64, true>,
                         cudaFuncAttributeMaxDynamicSharedMemorySize, SM3);

    // input -> fp16 (one pass)
    const int XN4 = BATCH * 512 * HWP / 4;     // 8388608
    f2h_kernel<<<(XN4 + 255) / 256, 256>>>(x, x16, XN4);

    // layer 1: 512 -> 256
    conv_mma_kernel<512, 256, false><<<dim3(512, 2), 256, SM1>>>(
        x16, w1, b1, buf1, nullptr, nullptr, nullptr, 0);
    gn_part_kernel<<<32 * 16, 256>>>(buf1, gnpart, 32, 16);
    gn_final_kernel<<<1, 32>>>(gnpart, mr, 16, 1.f / 524288.f);

    // layer 2: 256 -> 128 (GN1+ReLU fused into B staging)
    conv_mma_kernel<256, 128, true><<<dim3(512, 1), 256, SM2>>>(
        buf1, w2, b2, buf2, mr, g1w, g1b, 8);
    gn_part_kernel<<<16 * 32, 256>>>(buf2, gnpart, 32, 32);
    gn_final_kernel<<<1, 16>>>(gnpart, mr, 32, 1.f / 524288.f);

    // layer 3: 128 -> 64 (GN2+ReLU fused into B staging)
    conv_mma_kernel<128, 64, true><<<dim3(512, 1), 256, SM3>>>(
        buf2, w3, b3, buf3, mr, g2w, g2b, 4);
    gn_part_kernel<<<16 * 32, 256>>>(buf3, gnpart, 16, 32);
    gn_final_kernel<<<1, 16>>>(gnpart, mr, 32, 1.f / 262144.f);

    // pooling (GN3+ReLU fused at read) + heads
    pool_acc_kernel<<<dim3(32, BATCH), 256>>>(buf3, masks, mr, g3w, g3b, partial, pcnt);
    heads_kernel<<<dim3(BATCH, KIDS), 64>>>(partial, pcnt, wb, bb, wc, bc, out);
}